// round 2
// baseline (speedup 1.0000x reference)
#include <cuda_runtime.h>
#include <cstdint>
#include <math.h>

// Problem constants
#define NH   8
#define ND   4096   // N_DST
#define NS   4096   // N_SRC
#define DIM  512    // IN_DIM == HIDDEN

// Per-head scratch (device globals: allocation-free, graph-capturable).
// Heads are processed sequentially on the stream, so one head's buffers
// can be reused by the next. Total: 96 MB.
__device__ float g_Q[(size_t)ND * DIM];     // 8 MB
__device__ float g_K[(size_t)NS * DIM];     // 8 MB
__device__ float g_V[(size_t)NS * DIM];     // 8 MB
__device__ float g_O[(size_t)ND * DIM];     // 8 MB
__device__ float g_S[(size_t)ND * NS];      // 64 MB

// ---------------------------------------------------------------------------
// tf32 helpers
// ---------------------------------------------------------------------------
__device__ __forceinline__ uint32_t f2tf32(float f) {
    uint32_t u;
    asm("cvt.rna.tf32.f32 %0, %1;" : "=r"(u) : "f"(f));
    return u;
}

__device__ __forceinline__ void mma_tf32(float* c, const uint32_t* a, const uint32_t* b) {
    asm volatile(
        "mma.sync.aligned.m16n8k8.row.col.f32.tf32.tf32.f32 "
        "{%0,%1,%2,%3}, {%4,%5,%6,%7}, {%8,%9}, {%0,%1,%2,%3};"
        : "+f"(c[0]), "+f"(c[1]), "+f"(c[2]), "+f"(c[3])
        : "r"(a[0]), "r"(a[1]), "r"(a[2]), "r"(a[3]),
          "r"(b[0]), "r"(b[1]));
}

// ---------------------------------------------------------------------------
// tf32 tensor-core GEMM:  C = A (MxK, row-major) @ B
//   B_TRANS=false: B is KxN row-major     (NN)
//   B_TRANS=true : B is NxK row-major, computes A @ B^T   (NT)
// Tile: 128x64, BK=32, 256 threads, 8 warps in 4(M) x 2(N), warp tile 32x32.
// ---------------------------------------------------------------------------
constexpr int BM = 128, BN = 64, BK = 32, NTHREADS = 256;
constexpr int BK_PAD = 36;
constexpr int BN_PAD = 68;

template<bool B_TRANS, bool ADD_BIAS, bool SCALE>
__global__ __launch_bounds__(NTHREADS)
void tf32_gemm(const float* __restrict__ A, const float* __restrict__ B,
               const float* __restrict__ bias, float* __restrict__ C,
               int M, int N, int K, float scale)
{
    __shared__ uint32_t As[BM][BK_PAD];
    __shared__ uint32_t Bs[B_TRANS ? BN : BK][B_TRANS ? BK_PAD : BN_PAD];

    const int tid  = threadIdx.x;
    const int lane = tid & 31;
    const int warp = tid >> 5;
    const int wm   = warp & 3;      // 0..3 -> m offset wm*32
    const int wn   = warp >> 2;     // 0..1 -> n offset wn*32
    const int g    = lane >> 2;     // groupID 0..7
    const int t4   = lane & 3;      // threadID_in_group 0..3

    const int m0 = blockIdx.y * BM;
    const int n0 = blockIdx.x * BN;

    float acc[2][4][4];
    #pragma unroll
    for (int mi = 0; mi < 2; ++mi)
        #pragma unroll
        for (int ni = 0; ni < 4; ++ni)
            #pragma unroll
            for (int j = 0; j < 4; ++j) acc[mi][ni][j] = 0.f;

    for (int k0 = 0; k0 < K; k0 += BK) {
        // --- load A tile: 128 rows x 32 cols ---
        {
            const int r  = tid >> 3;   // 0..31
            const int c4 = tid & 7;    // 0..7
            #pragma unroll
            for (int it = 0; it < 4; ++it) {
                const float4 vv = *reinterpret_cast<const float4*>(
                    A + (size_t)(m0 + r + it * 32) * K + k0 + c4 * 4);
                As[r + it * 32][c4 * 4 + 0] = f2tf32(vv.x);
                As[r + it * 32][c4 * 4 + 1] = f2tf32(vv.y);
                As[r + it * 32][c4 * 4 + 2] = f2tf32(vv.z);
                As[r + it * 32][c4 * 4 + 3] = f2tf32(vv.w);
            }
        }
        // --- load B tile ---
        if (!B_TRANS) {
            int idx = tid;
            #pragma unroll
            for (int it = 0; it < 2; ++it, idx += NTHREADS) {
                const int r  = idx >> 4;   // 0..31
                const int c4 = idx & 15;   // 0..15
                const float4 vv = *reinterpret_cast<const float4*>(
                    B + (size_t)(k0 + r) * N + n0 + c4 * 4);
                Bs[r][c4 * 4 + 0] = f2tf32(vv.x);
                Bs[r][c4 * 4 + 1] = f2tf32(vv.y);
                Bs[r][c4 * 4 + 2] = f2tf32(vv.z);
                Bs[r][c4 * 4 + 3] = f2tf32(vv.w);
            }
        } else {
            int idx = tid;
            #pragma unroll
            for (int it = 0; it < 2; ++it, idx += NTHREADS) {
                const int r  = idx >> 3;   // 0..63
                const int c4 = idx & 7;    // 0..7
                const float4 vv = *reinterpret_cast<const float4*>(
                    B + (size_t)(n0 + r) * K + k0 + c4 * 4);
                Bs[r][c4 * 4 + 0] = f2tf32(vv.x);
                Bs[r][c4 * 4 + 1] = f2tf32(vv.y);
                Bs[r][c4 * 4 + 2] = f2tf32(vv.z);
                Bs[r][c4 * 4 + 3] = f2tf32(vv.w);
            }
        }
        __syncthreads();

        #pragma unroll
        for (int kk = 0; kk < BK; kk += 8) {
            uint32_t af[2][4], bf[4][2];
            #pragma unroll
            for (int mi = 0; mi < 2; ++mi) {
                const int rb = wm * 32 + mi * 16;
                af[mi][0] = As[rb + g    ][kk + t4    ];
                af[mi][1] = As[rb + g + 8][kk + t4    ];
                af[mi][2] = As[rb + g    ][kk + t4 + 4];
                af[mi][3] = As[rb + g + 8][kk + t4 + 4];
            }
            #pragma unroll
            for (int ni = 0; ni < 4; ++ni) {
                const int cb = wn * 32 + ni * 8 + g;
                if (B_TRANS) {
                    bf[ni][0] = Bs[cb][kk + t4];
                    bf[ni][1] = Bs[cb][kk + t4 + 4];
                } else {
                    bf[ni][0] = Bs[kk + t4    ][cb];
                    bf[ni][1] = Bs[kk + t4 + 4][cb];
                }
            }
            #pragma unroll
            for (int mi = 0; mi < 2; ++mi)
                #pragma unroll
                for (int ni = 0; ni < 4; ++ni)
                    mma_tf32(acc[mi][ni], af[mi], bf[ni]);
        }
        __syncthreads();
    }

    // --- epilogue ---
    #pragma unroll
    for (int mi = 0; mi < 2; ++mi) {
        #pragma unroll
        for (int ni = 0; ni < 4; ++ni) {
            const int r = m0 + wm * 32 + mi * 16 + g;
            const int c = n0 + wn * 32 + ni * 8 + 2 * t4;
            float v0 = acc[mi][ni][0], v1 = acc[mi][ni][1];
            float v2 = acc[mi][ni][2], v3 = acc[mi][ni][3];
            if (SCALE) { v0 *= scale; v1 *= scale; v2 *= scale; v3 *= scale; }
            if (ADD_BIAS) {
                const float b0 = bias[c], b1 = bias[c + 1];
                v0 += b0; v1 += b1; v2 += b0; v3 += b1;
            }
            *reinterpret_cast<float2*>(C + (size_t)r * N + c)       = make_float2(v0, v1);
            *reinterpret_cast<float2*>(C + (size_t)(r + 8) * N + c) = make_float2(v2, v3);
        }
    }
}

// ---------------------------------------------------------------------------
// Row softmax: one block per row of 4096 floats, 256 threads x 16 elems each
// ---------------------------------------------------------------------------
__global__ __launch_bounds__(256)
void softmax_kernel(float* __restrict__ S)
{
    const int tid = threadIdx.x;
    float* row = S + (size_t)blockIdx.x * NS;
    float4* row4 = reinterpret_cast<float4*>(row);

    float4 v[4];
    float m = -INFINITY;
    #pragma unroll
    for (int i = 0; i < 4; ++i) {
        v[i] = row4[i * 256 + tid];
        m = fmaxf(m, fmaxf(fmaxf(v[i].x, v[i].y), fmaxf(v[i].z, v[i].w)));
    }

    __shared__ float red[8];
    #pragma unroll
    for (int o = 16; o > 0; o >>= 1) m = fmaxf(m, __shfl_xor_sync(0xFFFFFFFFu, m, o));
    if ((tid & 31) == 0) red[tid >> 5] = m;
    __syncthreads();
    float M = -INFINITY;
    #pragma unroll
    for (int j = 0; j < 8; ++j) M = fmaxf(M, red[j]);
    __syncthreads();

    float s = 0.f;
    #pragma unroll
    for (int i = 0; i < 4; ++i) {
        v[i].x = expf(v[i].x - M);
        v[i].y = expf(v[i].y - M);
        v[i].z = expf(v[i].z - M);
        v[i].w = expf(v[i].w - M);
        s += v[i].x + v[i].y + v[i].z + v[i].w;
    }
    #pragma unroll
    for (int o = 16; o > 0; o >>= 1) s += __shfl_xor_sync(0xFFFFFFFFu, s, o);
    if ((tid & 31) == 0) red[tid >> 5] = s;
    __syncthreads();
    float tot = 0.f;
    #pragma unroll
    for (int j = 0; j < 8; ++j) tot += red[j];
    const float inv = 1.0f / tot;

    #pragma unroll
    for (int i = 0; i < 4; ++i) {
        v[i].x *= inv; v[i].y *= inv; v[i].z *= inv; v[i].w *= inv;
        row4[i * 256 + tid] = v[i];
    }
}

// ---------------------------------------------------------------------------
// Accumulate one head: out += elu(O) / NH   (FIRST=true initializes out)
// ---------------------------------------------------------------------------
template<bool FIRST>
__global__ __launch_bounds__(256)
void elu_acc_kernel(const float* __restrict__ O, float* __restrict__ out)
{
    const size_t idx = (size_t)blockIdx.x * blockDim.x + threadIdx.x;
    const float x = O[idx];
    const float e = (x > 0.f) ? x : expm1f(x);
    const float prev = FIRST ? 0.f : out[idx];
    out[idx] = prev + e * (1.0f / NH);
}

// ---------------------------------------------------------------------------
// kernel_launch: loop over heads, reusing per-head scratch (stream is serial)
// ---------------------------------------------------------------------------
extern "C" void kernel_launch(void* const* d_in, const int* in_sizes, int n_in,
                              void* d_out, int out_size)
{
    const float* emb_dest = (const float*)d_in[0];  // [4096, 512]
    const float* emb_src  = (const float*)d_in[1];  // [4096, 512]
    const float* feat_src = (const float*)d_in[2];  // [4096, 512]
    const float* Wq       = (const float*)d_in[3];  // [8, 512, 512]
    const float* bq       = (const float*)d_in[4];  // [8, 512]
    const float* Wk       = (const float*)d_in[5];
    const float* bk       = (const float*)d_in[6];
    const float* Wv       = (const float*)d_in[7];
    const float* bv       = (const float*)d_in[8];
    float* out = (float*)d_out;                     // [4096, 512]

    float *Q, *K, *V, *S, *O;
    cudaGetSymbolAddress((void**)&Q, g_Q);
    cudaGetSymbolAddress((void**)&K, g_K);
    cudaGetSymbolAddress((void**)&V, g_V);
    cudaGetSymbolAddress((void**)&S, g_S);
    cudaGetSymbolAddress((void**)&O, g_O);

    const dim3 blk(NTHREADS);
    const size_t sHW = (size_t)DIM * DIM;     // per-head weight stride
    const float scale = 0.04419417382415922f; // 1/sqrt(512)

    const dim3 gProj(DIM / BN, ND / BM);      // (8, 32)
    const dim3 gScore(NS / BN, ND / BM);      // (64, 32)
    const dim3 gAV(DIM / BN, ND / BM);        // (8, 32)

    for (int h = 0; h < NH; ++h) {
        const float* wq = Wq + (size_t)h * sHW;
        const float* wk = Wk + (size_t)h * sHW;
        const float* wv = Wv + (size_t)h * sHW;
        const float* bqh = bq + (size_t)h * DIM;
        const float* bkh = bk + (size_t)h * DIM;
        const float* bvh = bv + (size_t)h * DIM;

        // Projections: [4096,512] @ [512,512] + bias (NN)
        tf32_gemm<false, true, false><<<gProj, blk>>>(emb_dest, wq, bqh, Q,
            ND, DIM, DIM, 1.f);
        tf32_gemm<false, true, false><<<gProj, blk>>>(emb_src, wk, bkh, K,
            NS, DIM, DIM, 1.f);
        tf32_gemm<false, true, false><<<gProj, blk>>>(feat_src, wv, bvh, V,
            NS, DIM, DIM, 1.f);

        // Scores: S = Q @ K^T * scale  (NT)
        tf32_gemm<true, false, true><<<gScore, blk>>>(Q, K, nullptr, S,
            ND, NS, DIM, scale);

        // Row softmax over src dimension
        softmax_kernel<<<ND, 256>>>(S);

        // O = P @ V  (NN)
        tf32_gemm<false, false, false><<<gAV, blk>>>(S, V, nullptr, O,
            ND, DIM, NS, 1.f);

        // out += elu(O)/NH
        if (h == 0)
            elu_acc_kernel<true><<<(ND * DIM) / 256, 256>>>(O, out);
        else
            elu_acc_kernel<false><<<(ND * DIM) / 256, 256>>>(O, out);
    }
}

// round 5
// speedup vs baseline: 1.5896x; 1.5896x over previous
#include <cuda_runtime.h>
#include <cstdint>
#include <math.h>

#define NH   8
#define ND   4096
#define NS   4096
#define DIM  512

// Per-head scratch, reused across the serial head loop. Total 88 MB
// (96 MB footprint passed in R2; 256 MB+ kills the container).
__device__ float g_Q[(size_t)ND * DIM];     // 8 MB
__device__ float g_K[(size_t)NS * DIM];     // 8 MB
__device__ float g_V[(size_t)NS * DIM];     // 8 MB
__device__ float g_S[(size_t)ND * NS];      // 64 MB

// ---------------------------------------------------------------------------
// GEMM config: 128x128x32 block tile, 8 warps (2M x 4N), 64x32 warp tile,
// 3-stage cp.async pipeline. Raw fp32 bits are fed to tf32 mma (hw truncation).
// ---------------------------------------------------------------------------
constexpr int BM = 128, BN = 128, BK = 32, NT = 256, STAGES = 3;
constexpr int ASTR    = 36;   // A smem row stride (words): bank = 4g+t4, conflict-free
constexpr int BSTR_NN = 136;  // B (KxN) stride: bank = 8*t4+g, conflict-free
constexpr int BSTR_NT = 36;   // B (NxK) stride: bank = 4g+t4, conflict-free
constexpr int A_WORDS = BM * ASTR;  // 4608

// Compile-time trait constants (usable in both host and device code)
template<bool BT> struct GemmCfg;
template<> struct GemmCfg<false> {
    static constexpr int B_WORDS     = BK * BSTR_NN;              // 4352
    static constexpr int STAGE_WORDS = A_WORDS + B_WORDS;         // 8960
    static constexpr int SMEM_BYTES  = STAGES * STAGE_WORDS * 4;  // 107520
};
template<> struct GemmCfg<true> {
    static constexpr int B_WORDS     = BN * BSTR_NT;              // 4608
    static constexpr int STAGE_WORDS = A_WORDS + B_WORDS;         // 9216
    static constexpr int SMEM_BYTES  = STAGES * STAGE_WORDS * 4;  // 110592
};

// Epilogue modes
#define EPI_BIAS      0   // C = AB + bias
#define EPI_SCALE     1   // C = AB * scale
#define EPI_ELU_FIRST 2   // C = elu(AB)/NH
#define EPI_ELU_ACC   3   // C += elu(AB)/NH

__device__ __forceinline__ void cp16(uint32_t s, const void* g) {
    asm volatile("cp.async.cg.shared.global [%0], [%1], 16;" :: "r"(s), "l"(g));
}
__device__ __forceinline__ void cp_commit() {
    asm volatile("cp.async.commit_group;");
}

__device__ __forceinline__ void mma_tf32(float* c, const uint32_t* a, const uint32_t* b) {
    asm volatile(
        "mma.sync.aligned.m16n8k8.row.col.f32.tf32.tf32.f32 "
        "{%0,%1,%2,%3}, {%4,%5,%6,%7}, {%8,%9}, {%0,%1,%2,%3};"
        : "+f"(c[0]), "+f"(c[1]), "+f"(c[2]), "+f"(c[3])
        : "r"(a[0]), "r"(a[1]), "r"(a[2]), "r"(a[3]),
          "r"(b[0]), "r"(b[1]));
}

__device__ __forceinline__ float elu_f(float x) {
    return x > 0.f ? x : expm1f(x);
}

// ---------------------------------------------------------------------------
// C = A @ B (+bias); BT=false: B KxN (NN), BT=true: B NxK (NT: A@B^T)
// ---------------------------------------------------------------------------
template<bool BT, int EPI>
__global__ __launch_bounds__(NT, 2)
void gemm_k(const float* __restrict__ A, const float* __restrict__ B,
            const float* __restrict__ bias, float* __restrict__ C,
            int M, int N, int K, float scale)
{
    constexpr int STW = GemmCfg<BT>::STAGE_WORDS;
    extern __shared__ uint32_t smem[];

    const int tid  = threadIdx.x;
    const int warp = tid >> 5;
    const int wm   = warp >> 2;        // 0..1 -> m offset wm*64
    const int wn   = warp & 3;         // 0..3 -> n offset wn*32
    const int g    = (tid & 31) >> 2;  // 0..7
    const int t4   = tid & 3;          // 0..3

    const int m0 = blockIdx.y * BM;
    const int n0 = blockIdx.x * BN;

    const uint32_t sbase = (uint32_t)__cvta_generic_to_shared(smem);

    // cp.async thread mapping
    const int a_row = tid >> 3;            // 0..31 (+32i)
    const int a_col = (tid & 7) * 4;
    const int b_row = tid >> 5;            // NN: 0..7 (+8i)
    const int b_col = (tid & 31) * 4;

    const float* gA    = A + (size_t)(m0 + a_row) * K + a_col;
    const float* gB_nn = B + (size_t)b_row * N + n0 + b_col;        // + k0*N later
    const float* gB_nt = B + (size_t)(n0 + a_row) * K + a_col;      // + k0 later

    const uint32_t sA0    = sbase + (uint32_t)(a_row * ASTR + a_col) * 4;
    const uint32_t sB0_nn = sbase + (uint32_t)(A_WORDS + b_row * BSTR_NN + b_col) * 4;
    const uint32_t sB0_nt = sbase + (uint32_t)(A_WORDS + a_row * BSTR_NT + a_col) * 4;

    auto issue = [&](int st, int k0) {
        const uint32_t so = (uint32_t)(st * STW) * 4;
        const float* ga = gA + k0;
        #pragma unroll
        for (int i = 0; i < 4; ++i)
            cp16(sA0 + so + i * 32 * ASTR * 4, ga + (size_t)i * 32 * K);
        if (!BT) {
            const float* gb = gB_nn + (size_t)k0 * N;
            #pragma unroll
            for (int i = 0; i < 4; ++i)
                cp16(sB0_nn + so + i * 8 * BSTR_NN * 4, gb + (size_t)i * 8 * N);
        } else {
            const float* gb = gB_nt + k0;
            #pragma unroll
            for (int i = 0; i < 4; ++i)
                cp16(sB0_nt + so + i * 32 * BSTR_NT * 4, gb + (size_t)i * 32 * K);
        }
    };

    float acc[4][4][4];
    #pragma unroll
    for (int mi = 0; mi < 4; ++mi)
        #pragma unroll
        for (int ni = 0; ni < 4; ++ni)
            #pragma unroll
            for (int j = 0; j < 4; ++j) acc[mi][ni][j] = 0.f;

    const int nsteps = K / BK;

    #pragma unroll
    for (int s = 0; s < STAGES; ++s) { issue(s, s * BK); cp_commit(); }

    for (int ks = 0; ks < nsteps; ++ks) {
        asm volatile("cp.async.wait_group %0;" :: "n"(STAGES - 1));
        __syncthreads();

        const int st = ks % STAGES;
        const uint32_t* As = smem + st * STW;
        const uint32_t* Bs = As + A_WORDS;

        #pragma unroll
        for (int kk = 0; kk < BK; kk += 8) {
            uint32_t af[4][4], bf[4][2];
            #pragma unroll
            for (int mi = 0; mi < 4; ++mi) {
                const int rb = wm * 64 + mi * 16;
                af[mi][0] = As[(rb + g    ) * ASTR + kk + t4    ];
                af[mi][1] = As[(rb + g + 8) * ASTR + kk + t4    ];
                af[mi][2] = As[(rb + g    ) * ASTR + kk + t4 + 4];
                af[mi][3] = As[(rb + g + 8) * ASTR + kk + t4 + 4];
            }
            #pragma unroll
            for (int ni = 0; ni < 4; ++ni) {
                const int cb = wn * 32 + ni * 8 + g;
                if (BT) {
                    bf[ni][0] = Bs[cb * BSTR_NT + kk + t4    ];
                    bf[ni][1] = Bs[cb * BSTR_NT + kk + t4 + 4];
                } else {
                    bf[ni][0] = Bs[(kk + t4    ) * BSTR_NN + cb];
                    bf[ni][1] = Bs[(kk + t4 + 4) * BSTR_NN + cb];
                }
            }
            #pragma unroll
            for (int mi = 0; mi < 4; ++mi)
                #pragma unroll
                for (int ni = 0; ni < 4; ++ni)
                    mma_tf32(acc[mi][ni], af[mi], bf[ni]);
        }
        __syncthreads();

        const int kn = ks + STAGES;
        if (kn < nsteps) issue(st, kn * BK);
        cp_commit();
    }

    // --- epilogue ---
    #pragma unroll
    for (int mi = 0; mi < 4; ++mi) {
        #pragma unroll
        for (int ni = 0; ni < 4; ++ni) {
            const int r = m0 + wm * 64 + mi * 16 + g;
            const int c = n0 + wn * 32 + ni * 8 + 2 * t4;
            float v0 = acc[mi][ni][0], v1 = acc[mi][ni][1];
            float v2 = acc[mi][ni][2], v3 = acc[mi][ni][3];
            float* p0 = C + (size_t)r * N + c;
            float* p1 = C + (size_t)(r + 8) * N + c;
            if (EPI == EPI_SCALE) {
                v0 *= scale; v1 *= scale; v2 *= scale; v3 *= scale;
                *reinterpret_cast<float2*>(p0) = make_float2(v0, v1);
                *reinterpret_cast<float2*>(p1) = make_float2(v2, v3);
            } else if (EPI == EPI_BIAS) {
                const float b0 = bias[c], b1 = bias[c + 1];
                *reinterpret_cast<float2*>(p0) = make_float2(v0 + b0, v1 + b1);
                *reinterpret_cast<float2*>(p1) = make_float2(v2 + b0, v3 + b1);
            } else {
                float e0 = elu_f(v0) * (1.0f / NH), e1 = elu_f(v1) * (1.0f / NH);
                float e2 = elu_f(v2) * (1.0f / NH), e3 = elu_f(v3) * (1.0f / NH);
                if (EPI == EPI_ELU_ACC) {
                    const float2 o0 = *reinterpret_cast<float2*>(p0);
                    const float2 o1 = *reinterpret_cast<float2*>(p1);
                    e0 += o0.x; e1 += o0.y; e2 += o1.x; e3 += o1.y;
                }
                *reinterpret_cast<float2*>(p0) = make_float2(e0, e1);
                *reinterpret_cast<float2*>(p1) = make_float2(e2, e3);
            }
        }
    }
}

// ---------------------------------------------------------------------------
// Row softmax: one block per row of 4096 floats
// ---------------------------------------------------------------------------
__global__ __launch_bounds__(256)
void softmax_kernel(float* __restrict__ S)
{
    const int tid = threadIdx.x;
    float4* row4 = reinterpret_cast<float4*>(S + (size_t)blockIdx.x * NS);

    float4 v[4];
    float m = -INFINITY;
    #pragma unroll
    for (int i = 0; i < 4; ++i) {
        v[i] = row4[i * 256 + tid];
        m = fmaxf(m, fmaxf(fmaxf(v[i].x, v[i].y), fmaxf(v[i].z, v[i].w)));
    }

    __shared__ float red[8];
    #pragma unroll
    for (int o = 16; o > 0; o >>= 1) m = fmaxf(m, __shfl_xor_sync(0xFFFFFFFFu, m, o));
    if ((tid & 31) == 0) red[tid >> 5] = m;
    __syncthreads();
    float M = -INFINITY;
    #pragma unroll
    for (int j = 0; j < 8; ++j) M = fmaxf(M, red[j]);
    __syncthreads();

    float s = 0.f;
    #pragma unroll
    for (int i = 0; i < 4; ++i) {
        v[i].x = expf(v[i].x - M);
        v[i].y = expf(v[i].y - M);
        v[i].z = expf(v[i].z - M);
        v[i].w = expf(v[i].w - M);
        s += v[i].x + v[i].y + v[i].z + v[i].w;
    }
    #pragma unroll
    for (int o = 16; o > 0; o >>= 1) s += __shfl_xor_sync(0xFFFFFFFFu, s, o);
    if ((tid & 31) == 0) red[tid >> 5] = s;
    __syncthreads();
    float tot = 0.f;
    #pragma unroll
    for (int j = 0; j < 8; ++j) tot += red[j];
    const float inv = 1.0f / tot;

    #pragma unroll
    for (int i = 0; i < 4; ++i) {
        v[i].x *= inv; v[i].y *= inv; v[i].z *= inv; v[i].w *= inv;
        row4[i * 256 + tid] = v[i];
    }
}

// ---------------------------------------------------------------------------
extern "C" void kernel_launch(void* const* d_in, const int* in_sizes, int n_in,
                              void* d_out, int out_size)
{
    const float* emb_dest = (const float*)d_in[0];
    const float* emb_src  = (const float*)d_in[1];
    const float* feat_src = (const float*)d_in[2];
    const float* Wq       = (const float*)d_in[3];
    const float* bq       = (const float*)d_in[4];
    const float* Wk       = (const float*)d_in[5];
    const float* bk       = (const float*)d_in[6];
    const float* Wv       = (const float*)d_in[7];
    const float* bv       = (const float*)d_in[8];
    float* out = (float*)d_out;

    float *Q, *K, *V, *S;
    cudaGetSymbolAddress((void**)&Q, g_Q);
    cudaGetSymbolAddress((void**)&K, g_K);
    cudaGetSymbolAddress((void**)&V, g_V);
    cudaGetSymbolAddress((void**)&S, g_S);

    constexpr int SM_NN = GemmCfg<false>::SMEM_BYTES;  // 107520
    constexpr int SM_NT = GemmCfg<true>::SMEM_BYTES;   // 110592
    cudaFuncSetAttribute(gemm_k<false, EPI_BIAS>,      cudaFuncAttributeMaxDynamicSharedMemorySize, SM_NN);
    cudaFuncSetAttribute(gemm_k<true,  EPI_SCALE>,     cudaFuncAttributeMaxDynamicSharedMemorySize, SM_NT);
    cudaFuncSetAttribute(gemm_k<false, EPI_ELU_FIRST>, cudaFuncAttributeMaxDynamicSharedMemorySize, SM_NN);
    cudaFuncSetAttribute(gemm_k<false, EPI_ELU_ACC>,   cudaFuncAttributeMaxDynamicSharedMemorySize, SM_NN);

    const dim3 blk(NT);
    const size_t sHW = (size_t)DIM * DIM;
    const float scale = 0.04419417382415922f; // 1/sqrt(512)

    const dim3 gProj(DIM / BN, ND / BM);       // (4, 32)
    const dim3 gScore(NS / BN, ND / BM);       // (32, 32)
    const dim3 gAV(DIM / BN, ND / BM);         // (4, 32)

    for (int h = 0; h < NH; ++h) {
        const float* wq  = Wq + (size_t)h * sHW;
        const float* wk  = Wk + (size_t)h * sHW;
        const float* wv  = Wv + (size_t)h * sHW;
        const float* bqh = bq + (size_t)h * DIM;
        const float* bkh = bk + (size_t)h * DIM;
        const float* bvh = bv + (size_t)h * DIM;

        // Projections: [4096,512] @ [512,512] + bias (NN)
        gemm_k<false, EPI_BIAS><<<gProj, blk, SM_NN>>>(emb_dest, wq, bqh, Q,
            ND, DIM, DIM, 1.f);
        gemm_k<false, EPI_BIAS><<<gProj, blk, SM_NN>>>(emb_src, wk, bkh, K,
            NS, DIM, DIM, 1.f);
        gemm_k<false, EPI_BIAS><<<gProj, blk, SM_NN>>>(feat_src, wv, bvh, V,
            NS, DIM, DIM, 1.f);

        // S = Q @ K^T * scale
        gemm_k<true, EPI_SCALE><<<gScore, blk, SM_NT>>>(Q, K, nullptr, S,
            ND, NS, DIM, scale);

        softmax_kernel<<<ND, 256>>>(S);

        // out (+)= elu(S @ V)/NH
        if (h == 0)
            gemm_k<false, EPI_ELU_FIRST><<<gAV, blk, SM_NN>>>(S, V, nullptr, out,
                ND, DIM, NS, 1.f);
        else
            gemm_k<false, EPI_ELU_ACC><<<gAV, blk, SM_NN>>>(S, V, nullptr, out,
                ND, DIM, NS, 1.f);
    }
}

// round 6
// speedup vs baseline: 2.7094x; 1.7045x over previous
#include <cuda_runtime.h>
#include <cuda_fp16.h>
#include <cstdint>
#include <math.h>

#define NH   8
#define ND   4096
#define NS   4096
#define DIM  512

// fp16 scratch. Total 68 MB (96 MB footprint proven safe; 256 MB kills container).
__device__ __half g_Eh [(size_t)ND * DIM];        // 4 MB  emb_dest fp16
__device__ __half g_Esh[(size_t)NS * DIM];        // 4 MB  emb_src  fp16
__device__ __half g_Fh [(size_t)NS * DIM];        // 4 MB  feat_src fp16
__device__ __half g_Wqt[(size_t)NH * DIM * DIM];  // 4 MB  Wq^T per head
__device__ __half g_Wkt[(size_t)NH * DIM * DIM];  // 4 MB
__device__ __half g_Wvt[(size_t)NH * DIM * DIM];  // 4 MB
__device__ __half g_Q  [(size_t)ND * DIM];        // 4 MB  per-head
__device__ __half g_K  [(size_t)NS * DIM];        // 4 MB
__device__ __half g_Vt [(size_t)DIM * NS];        // 4 MB  V^T [f][src]
__device__ __half g_S  [(size_t)ND * NS];         // 32 MB scores/probs fp16

// ---------------------------------------------------------------------------
// NT fp16 GEMM: C = A(MxK, row-major fp16) @ B(NxK, row-major fp16)^T
// 128x128 block tile, BK=64 halves, 8 warps (2M x 4N), 64x32 warp tile,
// m16n8k16 f16 mma with fp32 accum, 3-stage cp.async pipeline.
// ---------------------------------------------------------------------------
constexpr int BM = 128, BN = 128, BK = 64, NT_THREADS = 256, STAGES = 3;
constexpr int STR = 36;                        // smem row stride in words (32 data + 4 pad)
constexpr int TILE_WORDS  = BM * STR;          // 4608
constexpr int STAGE_WORDS = 2 * TILE_WORDS;    // 9216 (A tile + B tile)
constexpr int GEMM_SMEM   = STAGES * STAGE_WORDS * 4;  // 110592 B

// Epilogue modes
#define EPI_BIAS_H    0   // C(half)[r*N+c]  = h(acc + bias[c])
#define EPI_BIAS_HT   1   // C(half)[c*M+r]  = h(acc + bias[c])   (transposed store)
#define EPI_SCALE_H   2   // C(half)[r*N+c]  = h(acc * scale)
#define EPI_ELU_FIRST 3   // C(float)        = elu(acc)/NH
#define EPI_ELU_ACC   4   // C(float)       += elu(acc)/NH

__device__ __forceinline__ void cp16(uint32_t s, const void* g) {
    asm volatile("cp.async.cg.shared.global [%0], [%1], 16;" :: "r"(s), "l"(g));
}
__device__ __forceinline__ void cp_commit() {
    asm volatile("cp.async.commit_group;");
}
__device__ __forceinline__ void mma_f16(float* c, const uint32_t* a, const uint32_t* b) {
    asm volatile(
        "mma.sync.aligned.m16n8k16.row.col.f32.f16.f16.f32 "
        "{%0,%1,%2,%3}, {%4,%5,%6,%7}, {%8,%9}, {%0,%1,%2,%3};"
        : "+f"(c[0]), "+f"(c[1]), "+f"(c[2]), "+f"(c[3])
        : "r"(a[0]), "r"(a[1]), "r"(a[2]), "r"(a[3]),
          "r"(b[0]), "r"(b[1]));
}
__device__ __forceinline__ float elu_f(float x) { return x > 0.f ? x : expm1f(x); }

template<int EPI>
__global__ __launch_bounds__(NT_THREADS, 2)
void gemm_nt(const __half* __restrict__ A, const __half* __restrict__ B,
             const float* __restrict__ bias, void* __restrict__ Cv,
             int M, int N, int K, float scale)
{
    extern __shared__ uint32_t smem[];

    const int tid  = threadIdx.x;
    const int warp = tid >> 5;
    const int wm   = warp >> 2;        // 0..1 -> m offset wm*64
    const int wn   = warp & 3;         // 0..3 -> n offset wn*32
    const int g    = (tid & 31) >> 2;  // 0..7
    const int t4   = tid & 3;          // 0..3

    const int m0 = blockIdx.y * BM;
    const int n0 = blockIdx.x * BN;

    const uint32_t sbase = (uint32_t)__cvta_generic_to_shared(smem);

    // cp.async mapping: idx = tid + 256*i -> row = idx>>3 (row += 32 per i),
    // halves col = (idx&7)*8 (invariant over i)
    const int ld_row = tid >> 3;          // 0..31
    const int ld_c8  = (tid & 7) * 8;     // halves offset

    const __half* gA = A + (size_t)(m0 + ld_row) * K + ld_c8;
    const __half* gB = B + (size_t)(n0 + ld_row) * K + ld_c8;
    const uint32_t sA0 = sbase + (uint32_t)(ld_row * STR + (tid & 7) * 4) * 4;
    const uint32_t sB0 = sA0 + (uint32_t)TILE_WORDS * 4;

    auto issue = [&](int st, int k0) {
        const uint32_t so = (uint32_t)(st * STAGE_WORDS) * 4;
        #pragma unroll
        for (int i = 0; i < 4; ++i) {
            cp16(sA0 + so + i * 32 * STR * 4, gA + (size_t)i * 32 * K + k0);
            cp16(sB0 + so + i * 32 * STR * 4, gB + (size_t)i * 32 * K + k0);
        }
    };

    float acc[4][4][4];
    #pragma unroll
    for (int mi = 0; mi < 4; ++mi)
        #pragma unroll
        for (int ni = 0; ni < 4; ++ni)
            #pragma unroll
            for (int j = 0; j < 4; ++j) acc[mi][ni][j] = 0.f;

    const int nsteps = K / BK;

    #pragma unroll
    for (int s = 0; s < STAGES; ++s) { issue(s, s * BK); cp_commit(); }

    for (int ks = 0; ks < nsteps; ++ks) {
        asm volatile("cp.async.wait_group %0;" :: "n"(STAGES - 1));
        __syncthreads();

        const int st = ks % STAGES;
        const uint32_t* As = smem + st * STAGE_WORDS;
        const uint32_t* Bs = As + TILE_WORDS;

        #pragma unroll
        for (int kk = 0; kk < BK; kk += 16) {
            const int wb = kk >> 1;  // word base within row
            uint32_t af[4][4], bf[4][2];
            #pragma unroll
            for (int mi = 0; mi < 4; ++mi) {
                const int rb = wm * 64 + mi * 16;
                const int b0 = (rb + g    ) * STR + wb + t4;
                const int b1 = (rb + g + 8) * STR + wb + t4;
                af[mi][0] = As[b0];     af[mi][1] = As[b1];
                af[mi][2] = As[b0 + 4]; af[mi][3] = As[b1 + 4];
            }
            #pragma unroll
            for (int ni = 0; ni < 4; ++ni) {
                const int cb = wn * 32 + ni * 8 + g;
                const int bb = cb * STR + wb + t4;
                bf[ni][0] = Bs[bb]; bf[ni][1] = Bs[bb + 4];
            }
            #pragma unroll
            for (int mi = 0; mi < 4; ++mi)
                #pragma unroll
                for (int ni = 0; ni < 4; ++ni)
                    mma_f16(acc[mi][ni], af[mi], bf[ni]);
        }
        __syncthreads();

        const int kn = ks + STAGES;
        if (kn < nsteps) issue(st, kn * BK);
        cp_commit();
    }

    // --- epilogue ---
    #pragma unroll
    for (int mi = 0; mi < 4; ++mi) {
        #pragma unroll
        for (int ni = 0; ni < 4; ++ni) {
            const int r = m0 + wm * 64 + mi * 16 + g;
            const int c = n0 + wn * 32 + ni * 8 + 2 * t4;
            float v0 = acc[mi][ni][0], v1 = acc[mi][ni][1];
            float v2 = acc[mi][ni][2], v3 = acc[mi][ni][3];
            if (EPI == EPI_BIAS_H) {
                __half* C = (__half*)Cv;
                const float b0 = bias[c], b1 = bias[c + 1];
                *reinterpret_cast<__half2*>(C + (size_t)r * N + c) =
                    __floats2half2_rn(v0 + b0, v1 + b1);
                *reinterpret_cast<__half2*>(C + (size_t)(r + 8) * N + c) =
                    __floats2half2_rn(v2 + b0, v3 + b1);
            } else if (EPI == EPI_BIAS_HT) {
                __half* C = (__half*)Cv;   // C[c][r], row stride M
                const float b0 = bias[c], b1 = bias[c + 1];
                C[(size_t)c * M + r]           = __float2half_rn(v0 + b0);
                C[(size_t)(c + 1) * M + r]     = __float2half_rn(v1 + b1);
                C[(size_t)c * M + r + 8]       = __float2half_rn(v2 + b0);
                C[(size_t)(c + 1) * M + r + 8] = __float2half_rn(v3 + b1);
            } else if (EPI == EPI_SCALE_H) {
                __half* C = (__half*)Cv;
                *reinterpret_cast<__half2*>(C + (size_t)r * N + c) =
                    __floats2half2_rn(v0 * scale, v1 * scale);
                *reinterpret_cast<__half2*>(C + (size_t)(r + 8) * N + c) =
                    __floats2half2_rn(v2 * scale, v3 * scale);
            } else {
                float* C = (float*)Cv;
                float e0 = elu_f(v0) * (1.0f / NH), e1 = elu_f(v1) * (1.0f / NH);
                float e2 = elu_f(v2) * (1.0f / NH), e3 = elu_f(v3) * (1.0f / NH);
                float* p0 = C + (size_t)r * N + c;
                float* p1 = C + (size_t)(r + 8) * N + c;
                if (EPI == EPI_ELU_ACC) {
                    const float2 o0 = *reinterpret_cast<float2*>(p0);
                    const float2 o1 = *reinterpret_cast<float2*>(p1);
                    e0 += o0.x; e1 += o0.y; e2 += o1.x; e3 += o1.y;
                }
                *reinterpret_cast<float2*>(p0) = make_float2(e0, e1);
                *reinterpret_cast<float2*>(p1) = make_float2(e2, e3);
            }
        }
    }
}

// ---------------------------------------------------------------------------
// fp16 row softmax: one block per row of 4096 halves; fp32 math
// ---------------------------------------------------------------------------
__global__ __launch_bounds__(256)
void softmax_h(__half* __restrict__ S)
{
    const int tid = threadIdx.x;
    uint4* row4 = reinterpret_cast<uint4*>(S + (size_t)blockIdx.x * NS);  // 512 uint4

    uint4 u[2];
    u[0] = row4[tid];
    u[1] = row4[tid + 256];

    float2 f[8];
    const __half2* hp = reinterpret_cast<const __half2*>(u);
    #pragma unroll
    for (int i = 0; i < 8; ++i) f[i] = __half22float2(hp[i]);

    float m = -INFINITY;
    #pragma unroll
    for (int i = 0; i < 8; ++i) m = fmaxf(m, fmaxf(f[i].x, f[i].y));

    __shared__ float red[8];
    #pragma unroll
    for (int o = 16; o > 0; o >>= 1) m = fmaxf(m, __shfl_xor_sync(0xFFFFFFFFu, m, o));
    if ((tid & 31) == 0) red[tid >> 5] = m;
    __syncthreads();
    float M = -INFINITY;
    #pragma unroll
    for (int j = 0; j < 8; ++j) M = fmaxf(M, red[j]);
    __syncthreads();

    float s = 0.f;
    #pragma unroll
    for (int i = 0; i < 8; ++i) {
        f[i].x = __expf(f[i].x - M);
        f[i].y = __expf(f[i].y - M);
        s += f[i].x + f[i].y;
    }
    #pragma unroll
    for (int o = 16; o > 0; o >>= 1) s += __shfl_xor_sync(0xFFFFFFFFu, s, o);
    if ((tid & 31) == 0) red[tid >> 5] = s;
    __syncthreads();
    float tot = 0.f;
    #pragma unroll
    for (int j = 0; j < 8; ++j) tot += red[j];
    const float inv = 1.0f / tot;

    __half2* ho = reinterpret_cast<__half2*>(u);
    #pragma unroll
    for (int i = 0; i < 8; ++i)
        ho[i] = __floats2half2_rn(f[i].x * inv, f[i].y * inv);
    row4[tid]       = u[0];
    row4[tid + 256] = u[1];
}

// ---------------------------------------------------------------------------
// Converters (run once per replay, ~25 MB total)
// ---------------------------------------------------------------------------
__global__ __launch_bounds__(256)
void f2h_kernel(const float* __restrict__ in, __half* __restrict__ out)
{
    const size_t i = ((size_t)blockIdx.x * 256 + threadIdx.x) * 4;
    const float4 v = *reinterpret_cast<const float4*>(in + i);
    __half2 h01 = __floats2half2_rn(v.x, v.y);
    __half2 h23 = __floats2half2_rn(v.z, v.w);
    uint2 packed;
    packed.x = *reinterpret_cast<uint32_t*>(&h01);
    packed.y = *reinterpret_cast<uint32_t*>(&h23);
    *reinterpret_cast<uint2*>(out + i) = packed;
}

// W[z][d][e] (fp32) -> Wt[z][e][d] (fp16), 32x32 smem tiles
__global__ __launch_bounds__(256)
void transpose_f2h(const float* __restrict__ W, __half* __restrict__ Wt)
{
    __shared__ float t[32][33];
    const size_t zo = (size_t)blockIdx.z * DIM * DIM;
    const int tx = threadIdx.x, ty = threadIdx.y;   // block (32, 8)
    const int x  = blockIdx.x * 32 + tx;            // e
    const int y0 = blockIdx.y * 32;                 // d
    #pragma unroll
    for (int j = 0; j < 4; ++j)
        t[ty + 8 * j][tx] = W[zo + (size_t)(y0 + ty + 8 * j) * DIM + x];
    __syncthreads();
    const int xo  = blockIdx.y * 32 + tx;           // d
    const int yo0 = blockIdx.x * 32;                // e
    #pragma unroll
    for (int j = 0; j < 4; ++j)
        Wt[zo + (size_t)(yo0 + ty + 8 * j) * DIM + xo] =
            __float2half_rn(t[tx][ty + 8 * j]);
}

// ---------------------------------------------------------------------------
extern "C" void kernel_launch(void* const* d_in, const int* in_sizes, int n_in,
                              void* d_out, int out_size)
{
    const float* emb_dest = (const float*)d_in[0];
    const float* emb_src  = (const float*)d_in[1];
    const float* feat_src = (const float*)d_in[2];
    const float* Wq       = (const float*)d_in[3];
    const float* bq       = (const float*)d_in[4];
    const float* Wk       = (const float*)d_in[5];
    const float* bk       = (const float*)d_in[6];
    const float* Wv       = (const float*)d_in[7];
    const float* bv       = (const float*)d_in[8];
    float* out = (float*)d_out;

    __half *Eh, *Esh, *Fh, *Wqt, *Wkt, *Wvt, *Q, *K, *Vt, *S;
    cudaGetSymbolAddress((void**)&Eh,  g_Eh);
    cudaGetSymbolAddress((void**)&Esh, g_Esh);
    cudaGetSymbolAddress((void**)&Fh,  g_Fh);
    cudaGetSymbolAddress((void**)&Wqt, g_Wqt);
    cudaGetSymbolAddress((void**)&Wkt, g_Wkt);
    cudaGetSymbolAddress((void**)&Wvt, g_Wvt);
    cudaGetSymbolAddress((void**)&Q,   g_Q);
    cudaGetSymbolAddress((void**)&K,   g_K);
    cudaGetSymbolAddress((void**)&Vt,  g_Vt);
    cudaGetSymbolAddress((void**)&S,   g_S);

    cudaFuncSetAttribute(gemm_nt<EPI_BIAS_H>,    cudaFuncAttributeMaxDynamicSharedMemorySize, GEMM_SMEM);
    cudaFuncSetAttribute(gemm_nt<EPI_BIAS_HT>,   cudaFuncAttributeMaxDynamicSharedMemorySize, GEMM_SMEM);
    cudaFuncSetAttribute(gemm_nt<EPI_SCALE_H>,   cudaFuncAttributeMaxDynamicSharedMemorySize, GEMM_SMEM);
    cudaFuncSetAttribute(gemm_nt<EPI_ELU_FIRST>, cudaFuncAttributeMaxDynamicSharedMemorySize, GEMM_SMEM);
    cudaFuncSetAttribute(gemm_nt<EPI_ELU_ACC>,   cudaFuncAttributeMaxDynamicSharedMemorySize, GEMM_SMEM);

    // One-time fp16 conversion of inputs
    f2h_kernel<<<(ND * DIM) / 1024, 256>>>(emb_dest, Eh);
    f2h_kernel<<<(NS * DIM) / 1024, 256>>>(emb_src, Esh);
    f2h_kernel<<<(NS * DIM) / 1024, 256>>>(feat_src, Fh);
    const dim3 gT(DIM / 32, DIM / 32, NH), bT(32, 8);
    transpose_f2h<<<gT, bT>>>(Wq, Wqt);
    transpose_f2h<<<gT, bT>>>(Wk, Wkt);
    transpose_f2h<<<gT, bT>>>(Wv, Wvt);

    const dim3 blk(NT_THREADS);
    const dim3 gProj(DIM / BN, ND / BM);    // (4, 32)
    const dim3 gScore(NS / BN, ND / BM);    // (32, 32)
    const dim3 gAV(DIM / BN, ND / BM);      // (4, 32)
    const size_t sW = (size_t)DIM * DIM;
    const float scale = 0.04419417382415922f;  // 1/sqrt(512)

    for (int h = 0; h < NH; ++h) {
        // Projections (NT vs transposed weights): Q/K row-major, V transposed
        gemm_nt<EPI_BIAS_H><<<gProj, blk, GEMM_SMEM>>>(
            Eh, Wqt + (size_t)h * sW, bq + (size_t)h * DIM, Q, ND, DIM, DIM, 1.f);
        gemm_nt<EPI_BIAS_H><<<gProj, blk, GEMM_SMEM>>>(
            Esh, Wkt + (size_t)h * sW, bk + (size_t)h * DIM, K, NS, DIM, DIM, 1.f);
        gemm_nt<EPI_BIAS_HT><<<gProj, blk, GEMM_SMEM>>>(
            Fh, Wvt + (size_t)h * sW, bv + (size_t)h * DIM, Vt, NS, DIM, DIM, 1.f);

        // S = h( (Q @ K^T) * scale )
        gemm_nt<EPI_SCALE_H><<<gScore, blk, GEMM_SMEM>>>(
            Q, K, nullptr, S, ND, NS, DIM, scale);

        softmax_h<<<ND, 256>>>(S);

        // out (+)= elu(S @ Vt^T)/NH
        if (h == 0)
            gemm_nt<EPI_ELU_FIRST><<<gAV, blk, GEMM_SMEM>>>(
                S, Vt, nullptr, out, ND, DIM, NS, 1.f);
        else
            gemm_nt<EPI_ELU_ACC><<<gAV, blk, GEMM_SMEM>>>(
                S, Vt, nullptr, out, ND, DIM, NS, 1.f);
    }
}

// round 8
// speedup vs baseline: 2.8693x; 1.0590x over previous
#include <cuda_runtime.h>
#include <cuda_fp16.h>
#include <cstdint>
#include <math.h>

#define NH   8
#define ND   4096
#define NS   4096
#define DIM  512

// fp16 scratch. Total 68 MB (same footprint as the passing R6 run).
__device__ __half g_Eh [(size_t)ND * DIM];        // 4 MB  emb_dest fp16
__device__ __half g_Esh[(size_t)NS * DIM];        // 4 MB  emb_src  fp16
__device__ __half g_Fh [(size_t)NS * DIM];        // 4 MB  feat_src fp16
__device__ __half g_Wqt[(size_t)NH * DIM * DIM];  // 4 MB  Wq^T per head
__device__ __half g_Wkt[(size_t)NH * DIM * DIM];  // 4 MB
__device__ __half g_Wvt[(size_t)NH * DIM * DIM];  // 4 MB
__device__ __half g_Q  [(size_t)ND * DIM];        // 4 MB  per-head
__device__ __half g_K  [(size_t)NS * DIM];        // 4 MB
__device__ __half g_Vt [(size_t)DIM * NS];        // 4 MB  V^T [f][src]
__device__ __half g_S  [(size_t)ND * NS];         // 32 MB scores/probs fp16

// ---------------------------------------------------------------------------
// NT fp16 GEMM: C = A(MxK fp16 row-major) @ B(NxK fp16 row-major)^T
// 128x128 tile, BK=64 halves, 8 warps (2M x 4N), 64x32 warp tile,
// m16n8k16 fp32-accum mma, ldmatrix.x4 fragment loads, 3-stage cp.async.
// ---------------------------------------------------------------------------
constexpr int BM = 128, BN = 128, BK = 64, NT_THREADS = 256, STAGES = 3;
constexpr int STR = 36;                        // smem row stride in words (32 data + 4 pad)
constexpr int TILE_WORDS  = BM * STR;          // 4608
constexpr int STAGE_WORDS = 2 * TILE_WORDS;    // 9216
constexpr int GEMM_SMEM   = STAGES * STAGE_WORDS * 4;  // 110592 B

#define EPI_BIAS_H    0
#define EPI_BIAS_HT   1
#define EPI_SCALE_H   2
#define EPI_ELU_FIRST 3
#define EPI_ELU_ACC   4

__device__ __forceinline__ void cp16(uint32_t s, const void* g) {
    asm volatile("cp.async.cg.shared.global [%0], [%1], 16;" :: "r"(s), "l"(g));
}
__device__ __forceinline__ void cp_commit() {
    asm volatile("cp.async.commit_group;");
}
__device__ __forceinline__ void ldsm_x4(uint32_t& r0, uint32_t& r1,
                                        uint32_t& r2, uint32_t& r3, uint32_t addr) {
    asm volatile("ldmatrix.sync.aligned.m8n8.x4.shared.b16 {%0,%1,%2,%3}, [%4];"
                 : "=r"(r0), "=r"(r1), "=r"(r2), "=r"(r3) : "r"(addr));
}
__device__ __forceinline__ void mma_f16(float* c, const uint32_t* a, const uint32_t* b) {
    asm volatile(
        "mma.sync.aligned.m16n8k16.row.col.f32.f16.f16.f32 "
        "{%0,%1,%2,%3}, {%4,%5,%6,%7}, {%8,%9}, {%0,%1,%2,%3};"
        : "+f"(c[0]), "+f"(c[1]), "+f"(c[2]), "+f"(c[3])
        : "r"(a[0]), "r"(a[1]), "r"(a[2]), "r"(a[3]),
          "r"(b[0]), "r"(b[1]));
}
__device__ __forceinline__ float elu_f(float x) { return x > 0.f ? x : expm1f(x); }

template<int EPI>
__device__ __forceinline__
void gemm_body(const __half* __restrict__ A, const __half* __restrict__ B,
               const float* __restrict__ bias, void* __restrict__ Cv,
               int M, int N, int K, float scale)
{
    extern __shared__ uint32_t smem[];

    const int tid  = threadIdx.x;
    const int lane = tid & 31;
    const int warp = tid >> 5;
    const int wm   = warp >> 2;        // 0..1
    const int wn   = warp & 3;         // 0..3
    const int g    = lane >> 2;
    const int t4   = lane & 3;

    const int m0 = blockIdx.y * BM;
    const int n0 = blockIdx.x * BN;

    const uint32_t sbase = (uint32_t)__cvta_generic_to_shared(smem);

    // cp.async mapping
    const int ld_row = tid >> 3;          // 0..31
    const int ld_c8  = (tid & 7) * 8;     // halves

    const __half* gA = A + (size_t)(m0 + ld_row) * K + ld_c8;
    const __half* gB = B + (size_t)(n0 + ld_row) * K + ld_c8;
    const uint32_t sA0 = sbase + (uint32_t)(ld_row * STR + (tid & 7) * 4) * 4;
    const uint32_t sB0 = sA0 + (uint32_t)TILE_WORDS * 4;

    auto issue = [&](int st, int k0) {
        const uint32_t so = (uint32_t)(st * STAGE_WORDS) * 4;
        #pragma unroll
        for (int i = 0; i < 4; ++i) {
            cp16(sA0 + so + i * 32 * STR * 4, gA + (size_t)i * 32 * K + k0);
            cp16(sB0 + so + i * 32 * STR * 4, gB + (size_t)i * 32 * K + k0);
        }
    };

    // ldmatrix lane bases (words, relative to tile start)
    const int la_row = (lane & 7) + ((lane >> 3) & 1) * 8;
    const int la_wo  = (lane >> 4) * 4;
    const int lb_row = (lane & 7) + (lane >> 4) * 8;
    const int lb_wo  = ((lane >> 3) & 1) * 4;
    const int aBase  = (wm * 64 + la_row) * STR + la_wo;
    const int bBase  = (wn * 32 + lb_row) * STR + lb_wo;

    float acc[4][4][4];
    #pragma unroll
    for (int mi = 0; mi < 4; ++mi)
        #pragma unroll
        for (int ni = 0; ni < 4; ++ni)
            #pragma unroll
            for (int j = 0; j < 4; ++j) acc[mi][ni][j] = 0.f;

    const int nsteps = K / BK;

    #pragma unroll
    for (int s = 0; s < STAGES - 1; ++s) { issue(s, s * BK); cp_commit(); }

    for (int ks = 0; ks < nsteps; ++ks) {
        __syncthreads();   // buffer (ks-1)%S fully consumed by all warps
        const int pref = ks + STAGES - 1;
        if (pref < nsteps) issue(pref % STAGES, pref * BK);
        cp_commit();
        asm volatile("cp.async.wait_group %0;" :: "n"(STAGES - 1));
        __syncthreads();   // buffer ks%S visible to all warps

        const int st = ks % STAGES;
        const uint32_t stA = sbase + (uint32_t)(st * STAGE_WORDS) * 4;
        const uint32_t stB = stA + (uint32_t)TILE_WORDS * 4;

        #pragma unroll
        for (int kk = 0; kk < BK; kk += 16) {
            const int wb = kk >> 1;
            uint32_t af[4][4], bf[4][2];
            #pragma unroll
            for (int mi = 0; mi < 4; ++mi)
                ldsm_x4(af[mi][0], af[mi][1], af[mi][2], af[mi][3],
                        stA + (uint32_t)(aBase + mi * 16 * STR + wb) * 4);
            #pragma unroll
            for (int np = 0; np < 2; ++np)
                ldsm_x4(bf[2 * np][0], bf[2 * np][1], bf[2 * np + 1][0], bf[2 * np + 1][1],
                        stB + (uint32_t)(bBase + np * 16 * STR + wb) * 4);
            #pragma unroll
            for (int mi = 0; mi < 4; ++mi)
                #pragma unroll
                for (int ni = 0; ni < 4; ++ni)
                    mma_f16(acc[mi][ni], af[mi], bf[ni]);
        }
    }

    // --- epilogue ---
    #pragma unroll
    for (int mi = 0; mi < 4; ++mi) {
        #pragma unroll
        for (int ni = 0; ni < 4; ++ni) {
            const int r = m0 + wm * 64 + mi * 16 + g;
            const int c = n0 + wn * 32 + ni * 8 + 2 * t4;
            float v0 = acc[mi][ni][0], v1 = acc[mi][ni][1];
            float v2 = acc[mi][ni][2], v3 = acc[mi][ni][3];
            if (EPI == EPI_BIAS_H) {
                __half* C = (__half*)Cv;
                const float b0 = bias[c], b1 = bias[c + 1];
                *reinterpret_cast<__half2*>(C + (size_t)r * N + c) =
                    __floats2half2_rn(v0 + b0, v1 + b1);
                *reinterpret_cast<__half2*>(C + (size_t)(r + 8) * N + c) =
                    __floats2half2_rn(v2 + b0, v3 + b1);
            } else if (EPI == EPI_BIAS_HT) {
                __half* C = (__half*)Cv;   // C[c][r], row stride M
                const float b0 = bias[c], b1 = bias[c + 1];
                C[(size_t)c * M + r]           = __float2half_rn(v0 + b0);
                C[(size_t)(c + 1) * M + r]     = __float2half_rn(v1 + b1);
                C[(size_t)c * M + r + 8]       = __float2half_rn(v2 + b0);
                C[(size_t)(c + 1) * M + r + 8] = __float2half_rn(v3 + b1);
            } else if (EPI == EPI_SCALE_H) {
                __half* C = (__half*)Cv;
                *reinterpret_cast<__half2*>(C + (size_t)r * N + c) =
                    __floats2half2_rn(v0 * scale, v1 * scale);
                *reinterpret_cast<__half2*>(C + (size_t)(r + 8) * N + c) =
                    __floats2half2_rn(v2 * scale, v3 * scale);
            } else {
                float* C = (float*)Cv;
                float e0 = elu_f(v0) * (1.0f / NH), e1 = elu_f(v1) * (1.0f / NH);
                float e2 = elu_f(v2) * (1.0f / NH), e3 = elu_f(v3) * (1.0f / NH);
                float* p0 = C + (size_t)r * N + c;
                float* p1 = C + (size_t)(r + 8) * N + c;
                if (EPI == EPI_ELU_ACC) {
                    const float2 o0 = *reinterpret_cast<float2*>(p0);
                    const float2 o1 = *reinterpret_cast<float2*>(p1);
                    e0 += o0.x; e1 += o0.y; e2 += o1.x; e3 += o1.y;
                }
                *reinterpret_cast<float2*>(p0) = make_float2(e0, e1);
                *reinterpret_cast<float2*>(p1) = make_float2(e2, e3);
            }
        }
    }
}

template<int EPI>
__global__ __launch_bounds__(NT_THREADS, 2)
void gemm_nt(const __half* __restrict__ A, const __half* __restrict__ B,
             const float* __restrict__ bias, void* __restrict__ Cv,
             int M, int N, int K, float scale)
{
    gemm_body<EPI>(A, B, bias, Cv, M, N, K, scale);
}

// Q and K projections fused in one launch (z selects operands; same epilogue)
__global__ __launch_bounds__(NT_THREADS, 2)
void proj_qk(const __half* __restrict__ Eh, const __half* __restrict__ Esh,
             const __half* __restrict__ Wqt, const __half* __restrict__ Wkt,
             const float* __restrict__ bq, const float* __restrict__ bk,
             __half* __restrict__ Q, __half* __restrict__ K)
{
    const bool isK = (blockIdx.z != 0);
    gemm_body<EPI_BIAS_H>(isK ? Esh : Eh, isK ? Wkt : Wqt,
                          isK ? bk : bq, isK ? (void*)K : (void*)Q,
                          ND, DIM, DIM, 1.f);
}

// ---------------------------------------------------------------------------
// fp16 row softmax: one block per row of 4096 halves; fp32 math
// ---------------------------------------------------------------------------
__global__ __launch_bounds__(256)
void softmax_h(__half* __restrict__ S)
{
    const int tid = threadIdx.x;
    uint4* row4 = reinterpret_cast<uint4*>(S + (size_t)blockIdx.x * NS);

    uint4 u[2];
    u[0] = row4[tid];
    u[1] = row4[tid + 256];

    float2 f[8];
    const __half2* hp = reinterpret_cast<const __half2*>(u);
    #pragma unroll
    for (int i = 0; i < 8; ++i) f[i] = __half22float2(hp[i]);

    float m = -INFINITY;
    #pragma unroll
    for (int i = 0; i < 8; ++i) m = fmaxf(m, fmaxf(f[i].x, f[i].y));

    __shared__ float red[8];
    #pragma unroll
    for (int o = 16; o > 0; o >>= 1) m = fmaxf(m, __shfl_xor_sync(0xFFFFFFFFu, m, o));
    if ((tid & 31) == 0) red[tid >> 5] = m;
    __syncthreads();
    float M = -INFINITY;
    #pragma unroll
    for (int j = 0; j < 8; ++j) M = fmaxf(M, red[j]);
    __syncthreads();

    float s = 0.f;
    #pragma unroll
    for (int i = 0; i < 8; ++i) {
        f[i].x = __expf(f[i].x - M);
        f[i].y = __expf(f[i].y - M);
        s += f[i].x + f[i].y;
    }
    #pragma unroll
    for (int o = 16; o > 0; o >>= 1) s += __shfl_xor_sync(0xFFFFFFFFu, s, o);
    if ((tid & 31) == 0) red[tid >> 5] = s;
    __syncthreads();
    float tot = 0.f;
    #pragma unroll
    for (int j = 0; j < 8; ++j) tot += red[j];
    const float inv = 1.0f / tot;

    __half2* ho = reinterpret_cast<__half2*>(u);
    #pragma unroll
    for (int i = 0; i < 8; ++i)
        ho[i] = __floats2half2_rn(f[i].x * inv, f[i].y * inv);
    row4[tid]       = u[0];
    row4[tid + 256] = u[1];
}

// ---------------------------------------------------------------------------
// Converters
// ---------------------------------------------------------------------------
__global__ __launch_bounds__(256)
void f2h_kernel(const float* __restrict__ in, __half* __restrict__ out)
{
    const size_t i = ((size_t)blockIdx.x * 256 + threadIdx.x) * 4;
    const float4 v = *reinterpret_cast<const float4*>(in + i);
    __half2 h01 = __floats2half2_rn(v.x, v.y);
    __half2 h23 = __floats2half2_rn(v.z, v.w);
    uint2 packed;
    packed.x = *reinterpret_cast<uint32_t*>(&h01);
    packed.y = *reinterpret_cast<uint32_t*>(&h23);
    *reinterpret_cast<uint2*>(out + i) = packed;
}

// W[z][d][e] (fp32) -> Wt[z][e][d] (fp16)
__global__ __launch_bounds__(256)
void transpose_f2h(const float* __restrict__ W, __half* __restrict__ Wt)
{
    __shared__ float t[32][33];
    const size_t zo = (size_t)blockIdx.z * DIM * DIM;
    const int tx = threadIdx.x, ty = threadIdx.y;   // block (32, 8)
    const int x  = blockIdx.x * 32 + tx;
    const int y0 = blockIdx.y * 32;
    #pragma unroll
    for (int j = 0; j < 4; ++j)
        t[ty + 8 * j][tx] = W[zo + (size_t)(y0 + ty + 8 * j) * DIM + x];
    __syncthreads();
    const int xo  = blockIdx.y * 32 + tx;
    const int yo0 = blockIdx.x * 32;
    #pragma unroll
    for (int j = 0; j < 4; ++j)
        Wt[zo + (size_t)(yo0 + ty + 8 * j) * DIM + xo] =
            __float2half_rn(t[tx][ty + 8 * j]);
}

// ---------------------------------------------------------------------------
extern "C" void kernel_launch(void* const* d_in, const int* in_sizes, int n_in,
                              void* d_out, int out_size)
{
    const float* emb_dest = (const float*)d_in[0];
    const float* emb_src  = (const float*)d_in[1];
    const float* feat_src = (const float*)d_in[2];
    const float* Wq       = (const float*)d_in[3];
    const float* bq       = (const float*)d_in[4];
    const float* Wk       = (const float*)d_in[5];
    const float* bk       = (const float*)d_in[6];
    const float* Wv       = (const float*)d_in[7];
    const float* bv       = (const float*)d_in[8];
    float* out = (float*)d_out;

    __half *Eh, *Esh, *Fh, *Wqt, *Wkt, *Wvt, *Q, *K, *Vt, *S;
    cudaGetSymbolAddress((void**)&Eh,  g_Eh);
    cudaGetSymbolAddress((void**)&Esh, g_Esh);
    cudaGetSymbolAddress((void**)&Fh,  g_Fh);
    cudaGetSymbolAddress((void**)&Wqt, g_Wqt);
    cudaGetSymbolAddress((void**)&Wkt, g_Wkt);
    cudaGetSymbolAddress((void**)&Wvt, g_Wvt);
    cudaGetSymbolAddress((void**)&Q,   g_Q);
    cudaGetSymbolAddress((void**)&K,   g_K);
    cudaGetSymbolAddress((void**)&Vt,  g_Vt);
    cudaGetSymbolAddress((void**)&S,   g_S);

    cudaFuncSetAttribute(proj_qk,                   cudaFuncAttributeMaxDynamicSharedMemorySize, GEMM_SMEM);
    cudaFuncSetAttribute(gemm_nt<EPI_BIAS_HT>,      cudaFuncAttributeMaxDynamicSharedMemorySize, GEMM_SMEM);
    cudaFuncSetAttribute(gemm_nt<EPI_SCALE_H>,      cudaFuncAttributeMaxDynamicSharedMemorySize, GEMM_SMEM);
    cudaFuncSetAttribute(gemm_nt<EPI_ELU_FIRST>,    cudaFuncAttributeMaxDynamicSharedMemorySize, GEMM_SMEM);
    cudaFuncSetAttribute(gemm_nt<EPI_ELU_ACC>,      cudaFuncAttributeMaxDynamicSharedMemorySize, GEMM_SMEM);

    // One-time fp16 conversion of inputs
    f2h_kernel<<<(ND * DIM) / 1024, 256>>>(emb_dest, Eh);
    f2h_kernel<<<(NS * DIM) / 1024, 256>>>(emb_src, Esh);
    f2h_kernel<<<(NS * DIM) / 1024, 256>>>(feat_src, Fh);
    const dim3 gT(DIM / 32, DIM / 32, NH), bT(32, 8);
    transpose_f2h<<<gT, bT>>>(Wq, Wqt);
    transpose_f2h<<<gT, bT>>>(Wk, Wkt);
    transpose_f2h<<<gT, bT>>>(Wv, Wvt);

    const dim3 blk(NT_THREADS);
    const dim3 gProjQK(DIM / BN, ND / BM, 2);  // (4, 32, 2) = 256 blocks
    const dim3 gProjV(DIM / BN, ND / BM);      // (4, 32)
    const dim3 gScore(NS / BN, ND / BM);       // (32, 32)
    const dim3 gAV(DIM / BN, ND / BM);         // (4, 32)
    const size_t sW = (size_t)DIM * DIM;
    const float scale = 0.04419417382415922f;  // 1/sqrt(512)

    for (int h = 0; h < NH; ++h) {
        proj_qk<<<gProjQK, blk, GEMM_SMEM>>>(
            Eh, Esh, Wqt + (size_t)h * sW, Wkt + (size_t)h * sW,
            bq + (size_t)h * DIM, bk + (size_t)h * DIM, Q, K);
        gemm_nt<EPI_BIAS_HT><<<gProjV, blk, GEMM_SMEM>>>(
            Fh, Wvt + (size_t)h * sW, bv + (size_t)h * DIM, Vt, NS, DIM, DIM, 1.f);

        // S = h( (Q @ K^T) * scale )
        gemm_nt<EPI_SCALE_H><<<gScore, blk, GEMM_SMEM>>>(
            Q, K, nullptr, S, ND, NS, DIM, scale);

        softmax_h<<<ND, 256>>>(S);

        // out (+)= elu(S @ Vt^T)/NH
        if (h == 0)
            gemm_nt<EPI_ELU_FIRST><<<gAV, blk, GEMM_SMEM>>>(
                S, Vt, nullptr, out, ND, DIM, NS, 1.f);
        else
            gemm_nt<EPI_ELU_ACC><<<gAV, blk, GEMM_SMEM>>>(
                S, Vt, nullptr, out, ND, DIM, NS, 1.f);
    }
}

// round 9
// speedup vs baseline: 3.2653x; 1.1380x over previous
#include <cuda_runtime.h>
#include <cuda_fp16.h>
#include <cstdint>
#include <math.h>

#define NH   8
#define ND   4096
#define NS   4096
#define DIM  512

// fp16 scratch, heads processed in PAIRS. Total 112 MB.
__device__ __half g_Eh [(size_t)ND * DIM];            // 4 MB  emb_dest fp16
__device__ __half g_Esh[(size_t)NS * DIM];            // 4 MB  emb_src  fp16
__device__ __half g_Fh [(size_t)NS * DIM];            // 4 MB  feat_src fp16
__device__ __half g_Wqt[(size_t)NH * DIM * DIM];      // 4 MB  Wq^T per head
__device__ __half g_Wkt[(size_t)NH * DIM * DIM];      // 4 MB
__device__ __half g_Wvt[(size_t)NH * DIM * DIM];      // 4 MB
__device__ __half g_Q  [(size_t)2 * ND * DIM];        // 8 MB  (2 heads)
__device__ __half g_K  [(size_t)2 * NS * DIM];        // 8 MB
__device__ __half g_Vt [(size_t)2 * DIM * NS];        // 8 MB  V^T [f][src]
__device__ __half g_S  [(size_t)2 * ND * NS];         // 64 MB scores/probs

// ---------------------------------------------------------------------------
// NT fp16 GEMM: C = A(MxK fp16 row-major) @ B(NxK fp16 row-major)^T
// 128x128 tile, BK=64 halves, 8 warps (2M x 4N), 64x32 warp tile,
// m16n8k16 fp32-accum mma, ldmatrix.x4 fragment loads, 3-stage cp.async.
// ---------------------------------------------------------------------------
constexpr int BM = 128, BN = 128, BK = 64, NT_THREADS = 256, STAGES = 3;
constexpr int STR = 36;                        // smem row stride in words
constexpr int TILE_WORDS  = BM * STR;          // 4608
constexpr int STAGE_WORDS = 2 * TILE_WORDS;    // 9216
constexpr int GEMM_SMEM   = STAGES * STAGE_WORDS * 4;  // 110592 B

#define EPI_BIAS_DUAL 0   // C(half) = h(acc + bias[c]); tstore picks [r][c] vs [c][r]
#define EPI_SCALE_H   1   // C(half)[r*N+c] = h(acc * scale)
#define EPI_ELU_ATOM  2   // atomicAdd(C(float)[r*N+c], elu(acc)/NH)

__device__ __forceinline__ void cp16(uint32_t s, const void* g) {
    asm volatile("cp.async.cg.shared.global [%0], [%1], 16;" :: "r"(s), "l"(g));
}
__device__ __forceinline__ void cp_commit() {
    asm volatile("cp.async.commit_group;");
}
__device__ __forceinline__ void ldsm_x4(uint32_t& r0, uint32_t& r1,
                                        uint32_t& r2, uint32_t& r3, uint32_t addr) {
    asm volatile("ldmatrix.sync.aligned.m8n8.x4.shared.b16 {%0,%1,%2,%3}, [%4];"
                 : "=r"(r0), "=r"(r1), "=r"(r2), "=r"(r3) : "r"(addr));
}
__device__ __forceinline__ void mma_f16(float* c, const uint32_t* a, const uint32_t* b) {
    asm volatile(
        "mma.sync.aligned.m16n8k16.row.col.f32.f16.f16.f32 "
        "{%0,%1,%2,%3}, {%4,%5,%6,%7}, {%8,%9}, {%0,%1,%2,%3};"
        : "+f"(c[0]), "+f"(c[1]), "+f"(c[2]), "+f"(c[3])
        : "r"(a[0]), "r"(a[1]), "r"(a[2]), "r"(a[3]),
          "r"(b[0]), "r"(b[1]));
}
__device__ __forceinline__ float elu_f(float x) { return x > 0.f ? x : expm1f(x); }

template<int EPI>
__device__ __forceinline__
void gemm_body(const __half* __restrict__ A, const __half* __restrict__ B,
               const float* __restrict__ bias, void* __restrict__ Cv,
               int M, int N, int K, float scale, bool tstore)
{
    extern __shared__ uint32_t smem[];

    const int tid  = threadIdx.x;
    const int lane = tid & 31;
    const int warp = tid >> 5;
    const int wm   = warp >> 2;        // 0..1
    const int wn   = warp & 3;         // 0..3
    const int g    = lane >> 2;
    const int t4   = lane & 3;

    const int m0 = blockIdx.y * BM;
    const int n0 = blockIdx.x * BN;

    const uint32_t sbase = (uint32_t)__cvta_generic_to_shared(smem);

    const int ld_row = tid >> 3;          // 0..31
    const int ld_c8  = (tid & 7) * 8;     // halves

    const __half* gA = A + (size_t)(m0 + ld_row) * K + ld_c8;
    const __half* gB = B + (size_t)(n0 + ld_row) * K + ld_c8;
    const uint32_t sA0 = sbase + (uint32_t)(ld_row * STR + (tid & 7) * 4) * 4;
    const uint32_t sB0 = sA0 + (uint32_t)TILE_WORDS * 4;

    auto issue = [&](int st, int k0) {
        const uint32_t so = (uint32_t)(st * STAGE_WORDS) * 4;
        #pragma unroll
        for (int i = 0; i < 4; ++i) {
            cp16(sA0 + so + i * 32 * STR * 4, gA + (size_t)i * 32 * K + k0);
            cp16(sB0 + so + i * 32 * STR * 4, gB + (size_t)i * 32 * K + k0);
        }
    };

    // ldmatrix lane bases (words, relative to tile start)
    const int la_row = (lane & 7) + ((lane >> 3) & 1) * 8;
    const int la_wo  = (lane >> 4) * 4;
    const int lb_row = (lane & 7) + (lane >> 4) * 8;
    const int lb_wo  = ((lane >> 3) & 1) * 4;
    const int aBase  = (wm * 64 + la_row) * STR + la_wo;
    const int bBase  = (wn * 32 + lb_row) * STR + lb_wo;

    float acc[4][4][4];
    #pragma unroll
    for (int mi = 0; mi < 4; ++mi)
        #pragma unroll
        for (int ni = 0; ni < 4; ++ni)
            #pragma unroll
            for (int j = 0; j < 4; ++j) acc[mi][ni][j] = 0.f;

    const int nsteps = K / BK;

    #pragma unroll
    for (int s = 0; s < STAGES - 1; ++s) { issue(s, s * BK); cp_commit(); }

    for (int ks = 0; ks < nsteps; ++ks) {
        __syncthreads();
        const int pref = ks + STAGES - 1;
        if (pref < nsteps) issue(pref % STAGES, pref * BK);
        cp_commit();
        asm volatile("cp.async.wait_group %0;" :: "n"(STAGES - 1));
        __syncthreads();

        const int st = ks % STAGES;
        const uint32_t stA = sbase + (uint32_t)(st * STAGE_WORDS) * 4;
        const uint32_t stB = stA + (uint32_t)TILE_WORDS * 4;

        #pragma unroll
        for (int kk = 0; kk < BK; kk += 16) {
            const int wb = kk >> 1;
            uint32_t af[4][4], bf[4][2];
            #pragma unroll
            for (int mi = 0; mi < 4; ++mi)
                ldsm_x4(af[mi][0], af[mi][1], af[mi][2], af[mi][3],
                        stA + (uint32_t)(aBase + mi * 16 * STR + wb) * 4);
            #pragma unroll
            for (int np = 0; np < 2; ++np)
                ldsm_x4(bf[2 * np][0], bf[2 * np][1], bf[2 * np + 1][0], bf[2 * np + 1][1],
                        stB + (uint32_t)(bBase + np * 16 * STR + wb) * 4);
            #pragma unroll
            for (int mi = 0; mi < 4; ++mi)
                #pragma unroll
                for (int ni = 0; ni < 4; ++ni)
                    mma_f16(acc[mi][ni], af[mi], bf[ni]);
        }
    }

    // --- epilogue ---
    #pragma unroll
    for (int mi = 0; mi < 4; ++mi) {
        #pragma unroll
        for (int ni = 0; ni < 4; ++ni) {
            const int r = m0 + wm * 64 + mi * 16 + g;
            const int c = n0 + wn * 32 + ni * 8 + 2 * t4;
            float v0 = acc[mi][ni][0], v1 = acc[mi][ni][1];
            float v2 = acc[mi][ni][2], v3 = acc[mi][ni][3];
            if (EPI == EPI_BIAS_DUAL) {
                __half* C = (__half*)Cv;
                const float b0 = bias[c], b1 = bias[c + 1];
                if (!tstore) {
                    *reinterpret_cast<__half2*>(C + (size_t)r * N + c) =
                        __floats2half2_rn(v0 + b0, v1 + b1);
                    *reinterpret_cast<__half2*>(C + (size_t)(r + 8) * N + c) =
                        __floats2half2_rn(v2 + b0, v3 + b1);
                } else {          // C[c][r], row stride M
                    C[(size_t)c * M + r]           = __float2half_rn(v0 + b0);
                    C[(size_t)(c + 1) * M + r]     = __float2half_rn(v1 + b1);
                    C[(size_t)c * M + r + 8]       = __float2half_rn(v2 + b0);
                    C[(size_t)(c + 1) * M + r + 8] = __float2half_rn(v3 + b1);
                }
            } else if (EPI == EPI_SCALE_H) {
                __half* C = (__half*)Cv;
                *reinterpret_cast<__half2*>(C + (size_t)r * N + c) =
                    __floats2half2_rn(v0 * scale, v1 * scale);
                *reinterpret_cast<__half2*>(C + (size_t)(r + 8) * N + c) =
                    __floats2half2_rn(v2 * scale, v3 * scale);
            } else {  // EPI_ELU_ATOM
                float* C = (float*)Cv;
                float* p0 = C + (size_t)r * N + c;
                float* p1 = C + (size_t)(r + 8) * N + c;
                atomicAdd(p0,     elu_f(v0) * (1.0f / NH));
                atomicAdd(p0 + 1, elu_f(v1) * (1.0f / NH));
                atomicAdd(p1,     elu_f(v2) * (1.0f / NH));
                atomicAdd(p1 + 1, elu_f(v3) * (1.0f / NH));
            }
        }
    }
}

// All 6 projections of a head pair in one launch.
// z = 0..5: kind = z%3 (0=Q, 1=K, 2=V), head = h0 + z/3
__global__ __launch_bounds__(NT_THREADS, 2)
void proj_all(const __half* __restrict__ Eh, const __half* __restrict__ Esh,
              const __half* __restrict__ Fh,
              const __half* __restrict__ Wqt, const __half* __restrict__ Wkt,
              const __half* __restrict__ Wvt,
              const float* __restrict__ bq, const float* __restrict__ bk,
              const float* __restrict__ bv,
              __half* __restrict__ Q, __half* __restrict__ K,
              __half* __restrict__ Vt, int h0)
{
    const int z    = blockIdx.z;
    const int kind = z % 3;
    const int hp   = z / 3;            // 0/1 within pair
    const int head = h0 + hp;
    const size_t sW = (size_t)DIM * DIM;
    const size_t sP = (size_t)ND * DIM;

    const __half* A = (kind == 0) ? Eh : (kind == 1) ? Esh : Fh;
    const __half* W = ((kind == 0) ? Wqt : (kind == 1) ? Wkt : Wvt) + (size_t)head * sW;
    const float* b  = ((kind == 0) ? bq  : (kind == 1) ? bk  : bv ) + (size_t)head * DIM;
    __half* C = (kind == 0) ? (Q + hp * sP) : (kind == 1) ? (K + hp * sP) : (Vt + hp * sP);

    gemm_body<EPI_BIAS_DUAL>(A, W, b, C, ND, DIM, DIM, 1.f, kind == 2);
}

// Score for a head pair: S[z] = h( (Q[z] @ K[z]^T) * scale )
__global__ __launch_bounds__(NT_THREADS, 2)
void score_pair(const __half* __restrict__ Q, const __half* __restrict__ K,
                __half* __restrict__ S, float scale)
{
    const int z = blockIdx.z;
    gemm_body<EPI_SCALE_H>(Q + (size_t)z * ND * DIM, K + (size_t)z * NS * DIM,
                           nullptr, S + (size_t)z * ND * NS, ND, NS, DIM, scale, false);
}

// AV for a head pair: out += elu(S[z] @ Vt[z]^T)/NH  (atomic accumulate)
__global__ __launch_bounds__(NT_THREADS, 2)
void av_pair(const __half* __restrict__ S, const __half* __restrict__ Vt,
             float* __restrict__ out)
{
    const int z = blockIdx.z;
    gemm_body<EPI_ELU_ATOM>(S + (size_t)z * ND * NS, Vt + (size_t)z * DIM * NS,
                            nullptr, out, ND, DIM, NS, 1.f, false);
}

// ---------------------------------------------------------------------------
// fp16 row softmax over both heads of a pair: one block per row
// ---------------------------------------------------------------------------
__global__ __launch_bounds__(256)
void softmax_h(__half* __restrict__ S)
{
    const int tid = threadIdx.x;
    uint4* row4 = reinterpret_cast<uint4*>(S + (size_t)blockIdx.x * NS);

    uint4 u[2];
    u[0] = row4[tid];
    u[1] = row4[tid + 256];

    float2 f[8];
    const __half2* hp = reinterpret_cast<const __half2*>(u);
    #pragma unroll
    for (int i = 0; i < 8; ++i) f[i] = __half22float2(hp[i]);

    float m = -INFINITY;
    #pragma unroll
    for (int i = 0; i < 8; ++i) m = fmaxf(m, fmaxf(f[i].x, f[i].y));

    __shared__ float red[8];
    #pragma unroll
    for (int o = 16; o > 0; o >>= 1) m = fmaxf(m, __shfl_xor_sync(0xFFFFFFFFu, m, o));
    if ((tid & 31) == 0) red[tid >> 5] = m;
    __syncthreads();
    float M = -INFINITY;
    #pragma unroll
    for (int j = 0; j < 8; ++j) M = fmaxf(M, red[j]);
    __syncthreads();

    float s = 0.f;
    #pragma unroll
    for (int i = 0; i < 8; ++i) {
        f[i].x = __expf(f[i].x - M);
        f[i].y = __expf(f[i].y - M);
        s += f[i].x + f[i].y;
    }
    #pragma unroll
    for (int o = 16; o > 0; o >>= 1) s += __shfl_xor_sync(0xFFFFFFFFu, s, o);
    if ((tid & 31) == 0) red[tid >> 5] = s;
    __syncthreads();
    float tot = 0.f;
    #pragma unroll
    for (int j = 0; j < 8; ++j) tot += red[j];
    const float inv = 1.0f / tot;

    __half2* ho = reinterpret_cast<__half2*>(u);
    #pragma unroll
    for (int i = 0; i < 8; ++i)
        ho[i] = __floats2half2_rn(f[i].x * inv, f[i].y * inv);
    row4[tid]       = u[0];
    row4[tid + 256] = u[1];
}

// ---------------------------------------------------------------------------
// Converters + zero
// ---------------------------------------------------------------------------
__global__ __launch_bounds__(256)
void f2h_kernel(const float* __restrict__ in, __half* __restrict__ out)
{
    const size_t i = ((size_t)blockIdx.x * 256 + threadIdx.x) * 4;
    const float4 v = *reinterpret_cast<const float4*>(in + i);
    __half2 h01 = __floats2half2_rn(v.x, v.y);
    __half2 h23 = __floats2half2_rn(v.z, v.w);
    uint2 packed;
    packed.x = *reinterpret_cast<uint32_t*>(&h01);
    packed.y = *reinterpret_cast<uint32_t*>(&h23);
    *reinterpret_cast<uint2*>(out + i) = packed;
}

__global__ __launch_bounds__(256)
void zero_kernel(float* __restrict__ out)
{
    const size_t i = ((size_t)blockIdx.x * 256 + threadIdx.x) * 4;
    *reinterpret_cast<float4*>(out + i) = make_float4(0.f, 0.f, 0.f, 0.f);
}

// W[z][d][e] (fp32) -> Wt[z][e][d] (fp16)
__global__ __launch_bounds__(256)
void transpose_f2h(const float* __restrict__ W, __half* __restrict__ Wt)
{
    __shared__ float t[32][33];
    const size_t zo = (size_t)blockIdx.z * DIM * DIM;
    const int tx = threadIdx.x, ty = threadIdx.y;   // block (32, 8)
    const int x  = blockIdx.x * 32 + tx;
    const int y0 = blockIdx.y * 32;
    #pragma unroll
    for (int j = 0; j < 4; ++j)
        t[ty + 8 * j][tx] = W[zo + (size_t)(y0 + ty + 8 * j) * DIM + x];
    __syncthreads();
    const int xo  = blockIdx.y * 32 + tx;
    const int yo0 = blockIdx.x * 32;
    #pragma unroll
    for (int j = 0; j < 4; ++j)
        Wt[zo + (size_t)(yo0 + ty + 8 * j) * DIM + xo] =
            __float2half_rn(t[tx][ty + 8 * j]);
}

// ---------------------------------------------------------------------------
extern "C" void kernel_launch(void* const* d_in, const int* in_sizes, int n_in,
                              void* d_out, int out_size)
{
    const float* emb_dest = (const float*)d_in[0];
    const float* emb_src  = (const float*)d_in[1];
    const float* feat_src = (const float*)d_in[2];
    const float* Wq       = (const float*)d_in[3];
    const float* bq       = (const float*)d_in[4];
    const float* Wk       = (const float*)d_in[5];
    const float* bk       = (const float*)d_in[6];
    const float* Wv       = (const float*)d_in[7];
    const float* bv       = (const float*)d_in[8];
    float* out = (float*)d_out;

    __half *Eh, *Esh, *Fh, *Wqt, *Wkt, *Wvt, *Q, *K, *Vt, *S;
    cudaGetSymbolAddress((void**)&Eh,  g_Eh);
    cudaGetSymbolAddress((void**)&Esh, g_Esh);
    cudaGetSymbolAddress((void**)&Fh,  g_Fh);
    cudaGetSymbolAddress((void**)&Wqt, g_Wqt);
    cudaGetSymbolAddress((void**)&Wkt, g_Wkt);
    cudaGetSymbolAddress((void**)&Wvt, g_Wvt);
    cudaGetSymbolAddress((void**)&Q,   g_Q);
    cudaGetSymbolAddress((void**)&K,   g_K);
    cudaGetSymbolAddress((void**)&Vt,  g_Vt);
    cudaGetSymbolAddress((void**)&S,   g_S);

    cudaFuncSetAttribute(proj_all,   cudaFuncAttributeMaxDynamicSharedMemorySize, GEMM_SMEM);
    cudaFuncSetAttribute(score_pair, cudaFuncAttributeMaxDynamicSharedMemorySize, GEMM_SMEM);
    cudaFuncSetAttribute(av_pair,    cudaFuncAttributeMaxDynamicSharedMemorySize, GEMM_SMEM);

    // One-time fp16 conversion + output zeroing
    f2h_kernel<<<(ND * DIM) / 1024, 256>>>(emb_dest, Eh);
    f2h_kernel<<<(NS * DIM) / 1024, 256>>>(emb_src, Esh);
    f2h_kernel<<<(NS * DIM) / 1024, 256>>>(feat_src, Fh);
    zero_kernel<<<(ND * DIM) / 1024, 256>>>(out);
    const dim3 gT(DIM / 32, DIM / 32, NH), bT(32, 8);
    transpose_f2h<<<gT, bT>>>(Wq, Wqt);
    transpose_f2h<<<gT, bT>>>(Wk, Wkt);
    transpose_f2h<<<gT, bT>>>(Wv, Wvt);

    const dim3 blk(NT_THREADS);
    const dim3 gProj(DIM / BN, ND / BM, 6);    // (4, 32, 6)  = 768 blocks
    const dim3 gScore(NS / BN, ND / BM, 2);    // (32, 32, 2) = 2048 blocks
    const dim3 gAV(DIM / BN, ND / BM, 2);      // (4, 32, 2)  = 256 blocks
    const float scale = 0.04419417382415922f;  // 1/sqrt(512)

    for (int h0 = 0; h0 < NH; h0 += 2) {
        proj_all<<<gProj, blk, GEMM_SMEM>>>(
            Eh, Esh, Fh, Wqt, Wkt, Wvt, bq, bk, bv, Q, K, Vt, h0);

        score_pair<<<gScore, blk, GEMM_SMEM>>>(Q, K, S, scale);

        softmax_h<<<2 * ND, 256>>>(S);

        av_pair<<<gAV, blk, GEMM_SMEM>>>(S, Vt, out);
    }
}